// round 14
// baseline (speedup 1.0000x reference)
#include <cuda_runtime.h>

#define N_NODES 100000
#define N_EDGES 1600000
#define R 4
#define NG 256
#define SEG (N_NODES * R)
#define SCAN_T 1024
#define NT2 ((SEG + SCAN_T - 1) / SCAN_T)

typedef unsigned long long u64;

// ---- scratch (zero-init at module load; launches self-restore) ----
__device__ int      g_cnt[SEG];
__device__ int      g_off[SEG + 1];
__device__ int      g_fill[SEG];
__device__ float    g_inv[SEG];
__device__ int      g_esrc[N_EDGES];
__device__ u64      g_state[NT2];
__device__ int      g_ticket;
__device__ float    g_h1[N_NODES * 16];
__device__ float    g_h2[N_NODES * 32];
__device__ unsigned g_pool[NG * 64];

// ---- packed f32x2 helpers ----
__device__ __forceinline__ void fma2(u64& d, u64 a, u64 b, u64 c) {
    asm("fma.rn.f32x2 %0, %1, %2, %3;" : "=l"(d) : "l"(a), "l"(b), "l"(c));
}
__device__ __forceinline__ void add2(u64& d, u64 a, u64 b) {
    asm("add.rn.f32x2 %0, %1, %2;" : "=l"(d) : "l"(a), "l"(b));
}
__device__ __forceinline__ void mul2(u64& d, u64 a, u64 b) {
    asm("mul.rn.f32x2 %0, %1, %2;" : "=l"(d) : "l"(a), "l"(b));
}
__device__ __forceinline__ u64 pack2(float x) {
    u64 d; unsigned u = __float_as_uint(x);
    asm("mov.b64 %0, {%1, %1};" : "=l"(d) : "r"(u));
    return d;
}

__device__ __forceinline__ unsigned enc(float v) {
    unsigned u = __float_as_uint(v);
    return (u & 0x80000000u) ? ~u : (u | 0x80000000u);
}
__device__ __forceinline__ float dec(unsigned u) {
    unsigned bits = (u & 0x80000000u) ? (u ^ 0x80000000u) : ~u;
    return __uint_as_float(bits);
}

// ---- 1. count ----
__global__ void count_kernel(const int* __restrict__ dst,
                             const int* __restrict__ et) {
    int e = blockIdx.x * blockDim.x + threadIdx.x;
    if (e < N_EDGES) atomicAdd(&g_cnt[dst[e] * R + et[e]], 1);
}

// ---- 2. decoupled-lookback scan; seeds off/fill/inv; zeroes cnt ----
__global__ __launch_bounds__(SCAN_T) void scan_kernel() {
    __shared__ int s[SCAN_T];
    __shared__ int s_tile;
    __shared__ int s_prefix;

    if (threadIdx.x == 0) s_tile = atomicAdd(&g_ticket, 1);
    __syncthreads();
    int tile = s_tile;
    int i = tile * SCAN_T + threadIdx.x;
    int v = (i < SEG) ? g_cnt[i] : 0;
    s[threadIdx.x] = v;
    __syncthreads();
    for (int d = 1; d < SCAN_T; d <<= 1) {
        int t = (threadIdx.x >= d) ? s[threadIdx.x - d] : 0;
        __syncthreads();
        s[threadIdx.x] += t;
        __syncthreads();
    }
    int incl  = s[threadIdx.x];
    int total = s[SCAN_T - 1];

    if (threadIdx.x == 0) {
        u64 st = (tile == 0) ? ((2ull << 32) | (unsigned)total)
                             : ((1ull << 32) | (unsigned)total);
        __threadfence();
        atomicExch(&g_state[tile], st);
        if (tile == 0) s_prefix = 0;
    }
    if (tile > 0 && threadIdx.x < 32) {
        int lane = threadIdx.x;
        int j = tile - 1;
        int agg = 0;
        while (true) {
            int idx = j - lane;
            u64 st = (idx >= 0) ? atomicAdd(&g_state[idx], 0ull) : (2ull << 32);
            unsigned flag = (unsigned)(st >> 32);
            unsigned invm = __ballot_sync(0xffffffffu, flag == 0);
            if (invm) continue;
            unsigned prefm = __ballot_sync(0xffffffffu, flag == 2);
            int stop = prefm ? (__ffs(prefm) - 1) : 32;
            int contrib = (lane <= stop) ? (int)(st & 0xffffffffu) : 0;
#pragma unroll
            for (int m = 16; m; m >>= 1) contrib += __shfl_xor_sync(~0u, contrib, m);
            agg += contrib;
            if (stop < 32) break;
            j -= 32;
        }
        if (lane == 0) {
            s_prefix = agg;
            __threadfence();
            atomicExch(&g_state[tile], (2ull << 32) | (unsigned)(agg + total));
        }
    }
    __syncthreads();
    int prefix = s_prefix;
    if (i < SEG) {
        int o = prefix + incl - v;
        g_off[i]  = o;
        g_fill[i] = o;
        g_inv[i]  = __fdividef(1.f, fmaxf((float)v, 1.f));
        g_cnt[i]  = 0;
    }
    if (i == SEG - 1) g_off[SEG] = N_EDGES;
}

// ---- 3. fill CSR; restore scan state ----
__global__ void fill_kernel(const int* __restrict__ src,
                            const int* __restrict__ dst,
                            const int* __restrict__ et) {
    int e = blockIdx.x * blockDim.x + threadIdx.x;
    if (e < N_EDGES) {
        int sg  = dst[e] * R + et[e];
        int pos = atomicAdd(&g_fill[sg], 1);
        g_esrc[pos] = src[e];
    }
    if (e < NT2) g_state[e] = 0ull;
    if (e == 0)  g_ticket = 0;
}

// ============================================================================
// Fused layer (round-12 structure): cross-task pipelined relation-partitioned
// gather + batched deg>4 tail.  POOL fuses segment-max pooling.
// ============================================================================
template <int DIN, int DOUT, int NB, bool RELU, bool POOL, int MINB>
__global__ __launch_bounds__(256, MINB) void layer_kernel(
        const float* __restrict__ xin,
        const float* __restrict__ W,
        const float* __restrict__ root,
        const float* __restrict__ bias,
        float* __restrict__ hout,
        const int* __restrict__ batch) {
    constexpr int F     = DIN / 8;            // floats per lane (2 or 4)
    constexpr int NU    = F / 2;              // u64 per lane (1 or 2)
    constexpr int NPW   = NB / 8;             // nodes per warp
    constexpr int OC    = DOUT / 4;
    constexpr int NGRP  = 256 / OC;
    constexpr int NPT   = NB / NGRP;
    constexpr int GSLOT = 8;
    static_assert(NB % 8 == 0 && NGRP * NPT == NB, "mapping");
    static_assert(F == 2 || F == 4, "lane feature width");
    static_assert(NPW * R <= 32, "offsets fit in one warp");

    __shared__ float    sAcc[NB][R + 1][DIN];
    __shared__ float    sW[(R + 1) * DIN * DOUT];
    __shared__ float    sBias[DOUT];
    __shared__ unsigned sPool[POOL ? GSLOT * 64 : 1];
    __shared__ int      sBatch[POOL ? NB : 1];

    for (int i = threadIdx.x; i < R * DIN * DOUT; i += 256) sW[i] = W[i];
    for (int i = threadIdx.x; i < DIN * DOUT; i += 256)
        sW[R * DIN * DOUT + i] = root[i];
    if (threadIdx.x < DOUT) sBias[threadIdx.x] = bias[threadIdx.x];

    const int node0 = blockIdx.x * NB;

    if (POOL) {
        for (int i = threadIdx.x; i < GSLOT * 64; i += 256) sPool[i] = 0u;
        if (threadIdx.x < NB) {
            int n = node0 + threadIdx.x;
            sBatch[threadIdx.x] = (n < N_NODES) ? batch[n] : 0;
        }
    }

    // ---- self rows (coalesced, outside the latency chain) ----
    for (int i = threadIdx.x; i < NB * (DIN / 2); i += 256) {
        int nn2 = i / (DIN / 2);
        int c   = i % (DIN / 2);
        int n2  = node0 + nn2;
        u64 v = (n2 < N_NODES)
              ? *reinterpret_cast<const u64*>(xin + n2 * DIN + c * 2) : 0ull;
        *reinterpret_cast<u64*>(&sAcc[nn2][R][c * 2]) = v;
    }

    const int wid   = threadIdx.x >> 5;
    const int lane  = threadIdx.x & 31;
    const int group = lane >> 3;              // relation 0..3
    const int fl    = lane & 7;               // feature sub-index

    // ---- preload this warp's offsets + invs into lane registers ----
    const int wnn     = wid * NPW;
    const int sb_base = (node0 + wnn) * R;
    int   o_l   = g_off[min(sb_base + lane, SEG)];
    int   extra = g_off[min(sb_base + NPW * R, SEG)];
    float inv_l = g_inv[min(sb_base + lane, SEG - 1)];

    // ---- pipelined task loop: task t = (node wnn+t, relation group) ----
    u64 acc[NU];
#pragma unroll
    for (int q = 0; q < NU; q++) acc[q] = 0ull;

    int o = __shfl_sync(~0u, o_l, group);
    int e = __shfl_sync(~0u, o_l, group + 1);
    int i0 = (o + 0 < e) ? g_esrc[o + 0] : -1;
    int i1 = (o + 1 < e) ? g_esrc[o + 1] : -1;
    int i2 = (o + 2 < e) ? g_esrc[o + 2] : -1;
    int i3 = (o + 3 < e) ? g_esrc[o + 3] : -1;

#pragma unroll
    for (int t = 0; t < NPW; t++) {
        // next task bounds (register shuffles, uniform flow)
        const bool hasNext = (t + 1 < NPW);
        int jn  = min((t + 1) * R + group, 31);
        int on  = __shfl_sync(~0u, o_l, jn);
        int ens = __shfl_sync(~0u, o_l, (jn + 1) & 31);
        int en  = ((jn + 1) == NPW * R) ? extra : ens;

        // x loads for current task's first batch (critical path)
        u64 v0[NU], v1[NU], v2[NU], v3[NU];
        if (F == 2) {
            v0[0] = (i0 >= 0) ? *reinterpret_cast<const u64*>(xin + i0 * DIN + fl * 2) : 0ull;
            v1[0] = (i1 >= 0) ? *reinterpret_cast<const u64*>(xin + i1 * DIN + fl * 2) : 0ull;
            v2[0] = (i2 >= 0) ? *reinterpret_cast<const u64*>(xin + i2 * DIN + fl * 2) : 0ull;
            v3[0] = (i3 >= 0) ? *reinterpret_cast<const u64*>(xin + i3 * DIN + fl * 2) : 0ull;
        } else {
            ulonglong2 z = make_ulonglong2(0ull, 0ull);
            ulonglong2 a0 = (i0 >= 0) ? *reinterpret_cast<const ulonglong2*>(xin + i0 * DIN + fl * 4) : z;
            ulonglong2 a1 = (i1 >= 0) ? *reinterpret_cast<const ulonglong2*>(xin + i1 * DIN + fl * 4) : z;
            ulonglong2 a2 = (i2 >= 0) ? *reinterpret_cast<const ulonglong2*>(xin + i2 * DIN + fl * 4) : z;
            ulonglong2 a3 = (i3 >= 0) ? *reinterpret_cast<const ulonglong2*>(xin + i3 * DIN + fl * 4) : z;
            v0[0] = a0.x; v0[1] = a0.y; v1[0] = a1.x; v1[1] = a1.y;
            v2[0] = a2.x; v2[1] = a2.y; v3[0] = a3.x; v3[1] = a3.y;
        }

        // prefetch next task's first esrc batch (overlaps x loads above)
        int n0 = (hasNext && on + 0 < en) ? g_esrc[on + 0] : -1;
        int n1 = (hasNext && on + 1 < en) ? g_esrc[on + 1] : -1;
        int n2 = (hasNext && on + 2 < en) ? g_esrc[on + 2] : -1;
        int n3 = (hasNext && on + 3 < en) ? g_esrc[on + 3] : -1;

#pragma unroll
        for (int q = 0; q < NU; q++) {
            add2(acc[q], acc[q], v0[q]);
            add2(acc[q], acc[q], v1[q]);
            add2(acc[q], acc[q], v2[q]);
            add2(acc[q], acc[q], v3[q]);
        }

        // batched tail for degree > 4 (groups of 4, proven guard pattern)
        for (int p = o + 4; p < e; p += 4) {
            int t0 = (p + 0 < e) ? g_esrc[p + 0] : -1;
            int t1 = (p + 1 < e) ? g_esrc[p + 1] : -1;
            int t2 = (p + 2 < e) ? g_esrc[p + 2] : -1;
            int t3 = (p + 3 < e) ? g_esrc[p + 3] : -1;
            if (F == 2) {
                u64 x0 = (t0 >= 0) ? *reinterpret_cast<const u64*>(xin + t0 * DIN + fl * 2) : 0ull;
                u64 x1 = (t1 >= 0) ? *reinterpret_cast<const u64*>(xin + t1 * DIN + fl * 2) : 0ull;
                u64 x2 = (t2 >= 0) ? *reinterpret_cast<const u64*>(xin + t2 * DIN + fl * 2) : 0ull;
                u64 x3 = (t3 >= 0) ? *reinterpret_cast<const u64*>(xin + t3 * DIN + fl * 2) : 0ull;
                add2(acc[0], acc[0], x0); add2(acc[0], acc[0], x1);
                add2(acc[0], acc[0], x2); add2(acc[0], acc[0], x3);
            } else {
                ulonglong2 z = make_ulonglong2(0ull, 0ull);
                ulonglong2 x0 = (t0 >= 0) ? *reinterpret_cast<const ulonglong2*>(xin + t0 * DIN + fl * 4) : z;
                ulonglong2 x1 = (t1 >= 0) ? *reinterpret_cast<const ulonglong2*>(xin + t1 * DIN + fl * 4) : z;
                ulonglong2 x2 = (t2 >= 0) ? *reinterpret_cast<const ulonglong2*>(xin + t2 * DIN + fl * 4) : z;
                ulonglong2 x3 = (t3 >= 0) ? *reinterpret_cast<const ulonglong2*>(xin + t3 * DIN + fl * 4) : z;
                add2(acc[0], acc[0], x0.x); add2(acc[1], acc[1], x0.y);
                add2(acc[0], acc[0], x1.x); add2(acc[1], acc[1], x1.y);
                add2(acc[0], acc[0], x2.x); add2(acc[1], acc[1], x2.y);
                add2(acc[0], acc[0], x3.x); add2(acc[1], acc[1], x3.y);
            }
        }

        // normalize + store
        float invf = __shfl_sync(~0u, inv_l, t * R + group);
        u64 iv = pack2(invf);
        int nn = wnn + t;
        if (F == 2) {
            mul2(acc[0], acc[0], iv);
            *reinterpret_cast<u64*>(&sAcc[nn][group][fl * 2]) = acc[0];
        } else {
            mul2(acc[0], acc[0], iv);
            mul2(acc[1], acc[1], iv);
            *reinterpret_cast<ulonglong2*>(&sAcc[nn][group][fl * 4]) =
                make_ulonglong2(acc[0], acc[1]);
        }
#pragma unroll
        for (int q = 0; q < NU; q++) acc[q] = 0ull;

        // shift pipeline state
        o = on; e = en;
        i0 = n0; i1 = n1; i2 = n2; i3 = n3;
    }
    __syncthreads();

    // ---- transform (packed f32x2) ----
    {
        int oc  = threadIdx.x % OC;
        int grp = threadIdx.x / OC;
        int o0  = oc * 4;
        int nb0 = grp * NPT;

        const u64* bb = reinterpret_cast<const u64*>(&sBias[o0]);
        u64 s01[NPT], s23[NPT];
#pragma unroll
        for (int k = 0; k < NPT; k++) { s01[k] = bb[0]; s23[k] = bb[1]; }

#pragma unroll
        for (int r = 0; r < R + 1; r++) {
#pragma unroll
            for (int i4 = 0; i4 < DIN / 4; i4++) {
                const float* wb = &sW[(r * DIN + i4 * 4) * DOUT + o0];
                ulonglong2 w0 = *reinterpret_cast<const ulonglong2*>(wb);
                ulonglong2 w1 = *reinterpret_cast<const ulonglong2*>(wb + DOUT);
                ulonglong2 w2 = *reinterpret_cast<const ulonglong2*>(wb + 2 * DOUT);
                ulonglong2 w3 = *reinterpret_cast<const ulonglong2*>(wb + 3 * DOUT);
#pragma unroll
                for (int k = 0; k < NPT; k++) {
                    float4 a = *reinterpret_cast<const float4*>(&sAcc[nb0 + k][r][i4 * 4]);
                    u64 aa;
                    aa = pack2(a.x); fma2(s01[k], aa, w0.x, s01[k]); fma2(s23[k], aa, w0.y, s23[k]);
                    aa = pack2(a.y); fma2(s01[k], aa, w1.x, s01[k]); fma2(s23[k], aa, w1.y, s23[k]);
                    aa = pack2(a.z); fma2(s01[k], aa, w2.x, s01[k]); fma2(s23[k], aa, w2.y, s23[k]);
                    aa = pack2(a.w); fma2(s01[k], aa, w3.x, s01[k]); fma2(s23[k], aa, w3.y, s23[k]);
                }
            }
        }
#pragma unroll
        for (int k = 0; k < NPT; k++) {
            int n = node0 + nb0 + k;
            if (n < N_NODES) {
                union { u64 q[2]; float f[4]; } sv;
                sv.q[0] = s01[k]; sv.q[1] = s23[k];
                if (RELU) {
#pragma unroll
                    for (int j = 0; j < 4; j++) sv.f[j] = fmaxf(sv.f[j], 0.f);
                }
                if (!POOL) {
                    *reinterpret_cast<float4*>(&hout[n * DOUT + o0]) =
                        make_float4(sv.f[0], sv.f[1], sv.f[2], sv.f[3]);
                } else {
                    int g  = sBatch[nb0 + k];
                    int gr = g - sBatch[0];
#pragma unroll
                    for (int j = 0; j < 4; j++) {
                        unsigned ev = enc(sv.f[j]);
                        if (gr >= 0 && gr < GSLOT)
                            atomicMax(&sPool[gr * 64 + o0 + j], ev);
                        else
                            atomicMax(&g_pool[g * 64 + o0 + j], ev);
                    }
                }
            }
        }
    }

    if (POOL) {
        __syncthreads();
        int g0 = sBatch[0];
        for (int i = threadIdx.x; i < GSLOT * 64; i += 256) {
            unsigned v = sPool[i];
            int g = g0 + i / 64;
            if (v != 0u && g < NG)
                atomicMax(&g_pool[g * 64 + (i & 63)], v);
        }
    }
}

// ---- decode + restore pool ----
__global__ void decode_kernel(float* __restrict__ out) {
    int i = blockIdx.x * blockDim.x + threadIdx.x;
    if (i < NG * 64) {
        unsigned u = g_pool[i];
        out[i] = (u == 0u) ? __int_as_float(0xff800000) : dec(u);
        g_pool[i] = 0u;
    }
}

extern "C" void kernel_launch(void* const* d_in, const int* in_sizes, int n_in,
                              void* d_out, int out_size) {
    const float* x     = (const float*)d_in[0];
    const int*   ei    = (const int*)d_in[1];
    const int*   src   = ei;
    const int*   dst   = ei + N_EDGES;
    const int*   et    = (const int*)d_in[2];
    const int*   batch = (const int*)d_in[3];
    const float* W1 = (const float*)d_in[4];
    const float* r1 = (const float*)d_in[5];
    const float* b1 = (const float*)d_in[6];
    const float* W2 = (const float*)d_in[7];
    const float* r2 = (const float*)d_in[8];
    const float* b2 = (const float*)d_in[9];
    const float* W3 = (const float*)d_in[10];
    const float* r3 = (const float*)d_in[11];
    const float* b3 = (const float*)d_in[12];
    float* out = (float*)d_out;

    float *h1p, *h2p;
    cudaGetSymbolAddress((void**)&h1p, g_h1);
    cudaGetSymbolAddress((void**)&h2p, g_h2);

    const int T = 256;

    count_kernel<<<(N_EDGES + T - 1) / T, T>>>(dst, et);         // 1
    scan_kernel<<<NT2, SCAN_T>>>();                              // 2
    fill_kernel<<<(N_EDGES + T - 1) / T, T>>>(src, dst, et);     // 3

    layer_kernel<16, 16, 64, true,  false, 4>                    // 4 <- profiled
        <<<(N_NODES + 63) / 64, T>>>(x,   W1, r1, b1, h1p, nullptr);
    layer_kernel<16, 32, 64, true,  false, 4>
        <<<(N_NODES + 63) / 64, T>>>(h1p, W2, r2, b2, h2p, nullptr);
    layer_kernel<32, 64, 16, false, true,  4>
        <<<(N_NODES + 15) / 16, T>>>(h2p, W3, r3, b3, nullptr, batch);

    decode_kernel<<<(NG * 64 + T - 1) / T, T>>>(out);
}

// round 15
// speedup vs baseline: 1.3347x; 1.3347x over previous
#include <cuda_runtime.h>

#define N_NODES 100000
#define N_EDGES 1600000
#define R 4
#define NG 256
#define SEG (N_NODES * R)
#define SCAN_T 1024
#define NT2 ((SEG + SCAN_T - 1) / SCAN_T)

typedef unsigned long long u64;

// ---- scratch (zero-init at module load; launches self-restore) ----
__device__ int      g_cnt[SEG];
__device__ int      g_off[SEG + 1];
__device__ int      g_fill[SEG];
__device__ float    g_inv[SEG];
__device__ int      g_esrc[N_EDGES];
__device__ u64      g_state[NT2];
__device__ int      g_ticket;
__device__ float    g_h1[N_NODES * 16];
__device__ float    g_h2[N_NODES * 32];
__device__ unsigned g_pool[NG * 64];

// ---- packed f32x2 helpers ----
__device__ __forceinline__ void fma2(u64& d, u64 a, u64 b, u64 c) {
    asm("fma.rn.f32x2 %0, %1, %2, %3;" : "=l"(d) : "l"(a), "l"(b), "l"(c));
}
__device__ __forceinline__ void add2(u64& d, u64 a, u64 b) {
    asm("add.rn.f32x2 %0, %1, %2;" : "=l"(d) : "l"(a), "l"(b));
}
__device__ __forceinline__ void mul2(u64& d, u64 a, u64 b) {
    asm("mul.rn.f32x2 %0, %1, %2;" : "=l"(d) : "l"(a), "l"(b));
}
__device__ __forceinline__ u64 pack2(float x) {
    u64 d; unsigned u = __float_as_uint(x);
    asm("mov.b64 %0, {%1, %1};" : "=l"(d) : "r"(u));
    return d;
}

__device__ __forceinline__ unsigned enc(float v) {
    unsigned u = __float_as_uint(v);
    return (u & 0x80000000u) ? ~u : (u | 0x80000000u);
}
__device__ __forceinline__ float dec(unsigned u) {
    unsigned bits = (u & 0x80000000u) ? (u ^ 0x80000000u) : ~u;
    return __uint_as_float(bits);
}

// ---- 1. count ----
__global__ void count_kernel(const int* __restrict__ dst,
                             const int* __restrict__ et) {
    int e = blockIdx.x * blockDim.x + threadIdx.x;
    if (e < N_EDGES) atomicAdd(&g_cnt[dst[e] * R + et[e]], 1);
}

// ---- 2. decoupled-lookback scan; seeds off/fill/inv; zeroes cnt ----
__global__ __launch_bounds__(SCAN_T) void scan_kernel() {
    __shared__ int s[SCAN_T];
    __shared__ int s_tile;
    __shared__ int s_prefix;

    if (threadIdx.x == 0) s_tile = atomicAdd(&g_ticket, 1);
    __syncthreads();
    int tile = s_tile;
    int i = tile * SCAN_T + threadIdx.x;
    int v = (i < SEG) ? g_cnt[i] : 0;
    s[threadIdx.x] = v;
    __syncthreads();
    for (int d = 1; d < SCAN_T; d <<= 1) {
        int t = (threadIdx.x >= d) ? s[threadIdx.x - d] : 0;
        __syncthreads();
        s[threadIdx.x] += t;
        __syncthreads();
    }
    int incl  = s[threadIdx.x];
    int total = s[SCAN_T - 1];

    if (threadIdx.x == 0) {
        u64 st = (tile == 0) ? ((2ull << 32) | (unsigned)total)
                             : ((1ull << 32) | (unsigned)total);
        __threadfence();
        atomicExch(&g_state[tile], st);
        if (tile == 0) s_prefix = 0;
    }
    if (tile > 0 && threadIdx.x < 32) {
        int lane = threadIdx.x;
        int j = tile - 1;
        int agg = 0;
        while (true) {
            int idx = j - lane;
            u64 st = (idx >= 0) ? atomicAdd(&g_state[idx], 0ull) : (2ull << 32);
            unsigned flag = (unsigned)(st >> 32);
            unsigned invm = __ballot_sync(0xffffffffu, flag == 0);
            if (invm) continue;
            unsigned prefm = __ballot_sync(0xffffffffu, flag == 2);
            int stop = prefm ? (__ffs(prefm) - 1) : 32;
            int contrib = (lane <= stop) ? (int)(st & 0xffffffffu) : 0;
#pragma unroll
            for (int m = 16; m; m >>= 1) contrib += __shfl_xor_sync(~0u, contrib, m);
            agg += contrib;
            if (stop < 32) break;
            j -= 32;
        }
        if (lane == 0) {
            s_prefix = agg;
            __threadfence();
            atomicExch(&g_state[tile], (2ull << 32) | (unsigned)(agg + total));
        }
    }
    __syncthreads();
    int prefix = s_prefix;
    if (i < SEG) {
        int o = prefix + incl - v;
        g_off[i]  = o;
        g_fill[i] = o;
        g_inv[i]  = __fdividef(1.f, fmaxf((float)v, 1.f));
        g_cnt[i]  = 0;
    }
    if (i == SEG - 1) g_off[SEG] = N_EDGES;
}

// ---- 3. fill CSR; restore scan state ----
__global__ void fill_kernel(const int* __restrict__ src,
                            const int* __restrict__ dst,
                            const int* __restrict__ et) {
    int e = blockIdx.x * blockDim.x + threadIdx.x;
    if (e < N_EDGES) {
        int sg  = dst[e] * R + et[e];
        int pos = atomicAdd(&g_fill[sg], 1);
        g_esrc[pos] = src[e];
    }
    if (e < NT2) g_state[e] = 0ull;
    if (e == 0)  g_ticket = 0;
}

// ============================================================================
// Fused layer, PERSISTENT: weights loaded once per block; grid-stride tile
// loop over node tiles.  Per tile: round-12 gather + transform (+POOL).
// ============================================================================
template <int DIN, int DOUT, int NB, bool RELU, bool POOL, int MINB>
__global__ __launch_bounds__(256, MINB) void layer_kernel(
        const float* __restrict__ xin,
        const float* __restrict__ W,
        const float* __restrict__ root,
        const float* __restrict__ bias,
        float* __restrict__ hout,
        const int* __restrict__ batch) {
    constexpr int F     = DIN / 8;            // floats per lane (2 or 4)
    constexpr int NU    = F / 2;              // u64 per lane (1 or 2)
    constexpr int NPW   = NB / 8;             // nodes per warp
    constexpr int OC    = DOUT / 4;
    constexpr int NGRP  = 256 / OC;
    constexpr int NPT   = NB / NGRP;
    constexpr int GSLOT = 8;
    constexpr int NTILES = (N_NODES + NB - 1) / NB;
    static_assert(NB % 8 == 0 && NGRP * NPT == NB, "mapping");
    static_assert(F == 2 || F == 4, "lane feature width");
    static_assert(NPW * R <= 32, "offsets fit in one warp");

    __shared__ float    sAcc[NB][R + 1][DIN];
    __shared__ float    sW[(R + 1) * DIN * DOUT];
    __shared__ float    sBias[DOUT];
    __shared__ unsigned sPool[POOL ? GSLOT * 64 : 1];
    __shared__ int      sBatch[POOL ? NB : 1];

    // ---- weights once per block ----
    for (int i = threadIdx.x; i < R * DIN * DOUT; i += 256) sW[i] = W[i];
    for (int i = threadIdx.x; i < DIN * DOUT; i += 256)
        sW[R * DIN * DOUT + i] = root[i];
    if (threadIdx.x < DOUT) sBias[threadIdx.x] = bias[threadIdx.x];
    __syncthreads();

    const int wid   = threadIdx.x >> 5;
    const int lane  = threadIdx.x & 31;
    const int group = lane >> 3;              // relation 0..3
    const int fl    = lane & 7;               // feature sub-index

    for (int tile = blockIdx.x; tile < NTILES; tile += gridDim.x) {
        const int node0 = tile * NB;

        if (POOL) {
            for (int i = threadIdx.x; i < GSLOT * 64; i += 256) sPool[i] = 0u;
            if (threadIdx.x < NB) {
                int n = node0 + threadIdx.x;
                sBatch[threadIdx.x] = (n < N_NODES) ? batch[n] : 0;
            }
        }

        // ---- self rows (coalesced, outside the latency chain) ----
        for (int i = threadIdx.x; i < NB * (DIN / 2); i += 256) {
            int nn2 = i / (DIN / 2);
            int c   = i % (DIN / 2);
            int n2  = node0 + nn2;
            u64 v = (n2 < N_NODES)
                  ? *reinterpret_cast<const u64*>(xin + n2 * DIN + c * 2) : 0ull;
            *reinterpret_cast<u64*>(&sAcc[nn2][R][c * 2]) = v;
        }

        // ---- preload this warp's offsets + invs into lane registers ----
        const int wnn     = wid * NPW;
        const int sb_base = (node0 + wnn) * R;
        int   o_l   = g_off[min(sb_base + lane, SEG)];
        int   extra = g_off[min(sb_base + NPW * R, SEG)];
        float inv_l = g_inv[min(sb_base + lane, SEG - 1)];

        // ---- pipelined task loop (round-12 gather) ----
        u64 acc[NU];
#pragma unroll
        for (int q = 0; q < NU; q++) acc[q] = 0ull;

        int o = __shfl_sync(~0u, o_l, group);
        int e = __shfl_sync(~0u, o_l, group + 1);
        int i0 = (o + 0 < e) ? g_esrc[o + 0] : -1;
        int i1 = (o + 1 < e) ? g_esrc[o + 1] : -1;
        int i2 = (o + 2 < e) ? g_esrc[o + 2] : -1;
        int i3 = (o + 3 < e) ? g_esrc[o + 3] : -1;

#pragma unroll
        for (int t = 0; t < NPW; t++) {
            const bool hasNext = (t + 1 < NPW);
            int jn  = min((t + 1) * R + group, 31);
            int on  = __shfl_sync(~0u, o_l, jn);
            int ens = __shfl_sync(~0u, o_l, (jn + 1) & 31);
            int en  = ((jn + 1) == NPW * R) ? extra : ens;

            u64 v0[NU], v1[NU], v2[NU], v3[NU];
            if (F == 2) {
                v0[0] = (i0 >= 0) ? *reinterpret_cast<const u64*>(xin + i0 * DIN + fl * 2) : 0ull;
                v1[0] = (i1 >= 0) ? *reinterpret_cast<const u64*>(xin + i1 * DIN + fl * 2) : 0ull;
                v2[0] = (i2 >= 0) ? *reinterpret_cast<const u64*>(xin + i2 * DIN + fl * 2) : 0ull;
                v3[0] = (i3 >= 0) ? *reinterpret_cast<const u64*>(xin + i3 * DIN + fl * 2) : 0ull;
            } else {
                ulonglong2 z = make_ulonglong2(0ull, 0ull);
                ulonglong2 a0 = (i0 >= 0) ? *reinterpret_cast<const ulonglong2*>(xin + i0 * DIN + fl * 4) : z;
                ulonglong2 a1 = (i1 >= 0) ? *reinterpret_cast<const ulonglong2*>(xin + i1 * DIN + fl * 4) : z;
                ulonglong2 a2 = (i2 >= 0) ? *reinterpret_cast<const ulonglong2*>(xin + i2 * DIN + fl * 4) : z;
                ulonglong2 a3 = (i3 >= 0) ? *reinterpret_cast<const ulonglong2*>(xin + i3 * DIN + fl * 4) : z;
                v0[0] = a0.x; v0[1] = a0.y; v1[0] = a1.x; v1[1] = a1.y;
                v2[0] = a2.x; v2[1] = a2.y; v3[0] = a3.x; v3[1] = a3.y;
            }

            int n0 = (hasNext && on + 0 < en) ? g_esrc[on + 0] : -1;
            int n1 = (hasNext && on + 1 < en) ? g_esrc[on + 1] : -1;
            int n2 = (hasNext && on + 2 < en) ? g_esrc[on + 2] : -1;
            int n3 = (hasNext && on + 3 < en) ? g_esrc[on + 3] : -1;

#pragma unroll
            for (int q = 0; q < NU; q++) {
                add2(acc[q], acc[q], v0[q]);
                add2(acc[q], acc[q], v1[q]);
                add2(acc[q], acc[q], v2[q]);
                add2(acc[q], acc[q], v3[q]);
            }

            for (int p = o + 4; p < e; p += 4) {
                int t0 = (p + 0 < e) ? g_esrc[p + 0] : -1;
                int t1 = (p + 1 < e) ? g_esrc[p + 1] : -1;
                int t2 = (p + 2 < e) ? g_esrc[p + 2] : -1;
                int t3 = (p + 3 < e) ? g_esrc[p + 3] : -1;
                if (F == 2) {
                    u64 x0 = (t0 >= 0) ? *reinterpret_cast<const u64*>(xin + t0 * DIN + fl * 2) : 0ull;
                    u64 x1 = (t1 >= 0) ? *reinterpret_cast<const u64*>(xin + t1 * DIN + fl * 2) : 0ull;
                    u64 x2 = (t2 >= 0) ? *reinterpret_cast<const u64*>(xin + t2 * DIN + fl * 2) : 0ull;
                    u64 x3 = (t3 >= 0) ? *reinterpret_cast<const u64*>(xin + t3 * DIN + fl * 2) : 0ull;
                    add2(acc[0], acc[0], x0); add2(acc[0], acc[0], x1);
                    add2(acc[0], acc[0], x2); add2(acc[0], acc[0], x3);
                } else {
                    ulonglong2 z = make_ulonglong2(0ull, 0ull);
                    ulonglong2 x0 = (t0 >= 0) ? *reinterpret_cast<const ulonglong2*>(xin + t0 * DIN + fl * 4) : z;
                    ulonglong2 x1 = (t1 >= 0) ? *reinterpret_cast<const ulonglong2*>(xin + t1 * DIN + fl * 4) : z;
                    ulonglong2 x2 = (t2 >= 0) ? *reinterpret_cast<const ulonglong2*>(xin + t2 * DIN + fl * 4) : z;
                    ulonglong2 x3 = (t3 >= 0) ? *reinterpret_cast<const ulonglong2*>(xin + t3 * DIN + fl * 4) : z;
                    add2(acc[0], acc[0], x0.x); add2(acc[1], acc[1], x0.y);
                    add2(acc[0], acc[0], x1.x); add2(acc[1], acc[1], x1.y);
                    add2(acc[0], acc[0], x2.x); add2(acc[1], acc[1], x2.y);
                    add2(acc[0], acc[0], x3.x); add2(acc[1], acc[1], x3.y);
                }
            }

            float invf = __shfl_sync(~0u, inv_l, t * R + group);
            u64 iv = pack2(invf);
            int nn = wnn + t;
            if (F == 2) {
                mul2(acc[0], acc[0], iv);
                *reinterpret_cast<u64*>(&sAcc[nn][group][fl * 2]) = acc[0];
            } else {
                mul2(acc[0], acc[0], iv);
                mul2(acc[1], acc[1], iv);
                *reinterpret_cast<ulonglong2*>(&sAcc[nn][group][fl * 4]) =
                    make_ulonglong2(acc[0], acc[1]);
            }
#pragma unroll
            for (int q = 0; q < NU; q++) acc[q] = 0ull;

            o = on; e = en;
            i0 = n0; i1 = n1; i2 = n2; i3 = n3;
        }
        __syncthreads();

        // ---- transform (packed f32x2) ----
        {
            int oc  = threadIdx.x % OC;
            int grp = threadIdx.x / OC;
            int o0  = oc * 4;
            int nb0 = grp * NPT;

            const u64* bb = reinterpret_cast<const u64*>(&sBias[o0]);
            u64 s01[NPT], s23[NPT];
#pragma unroll
            for (int k = 0; k < NPT; k++) { s01[k] = bb[0]; s23[k] = bb[1]; }

#pragma unroll
            for (int r = 0; r < R + 1; r++) {
#pragma unroll
                for (int i4 = 0; i4 < DIN / 4; i4++) {
                    const float* wb = &sW[(r * DIN + i4 * 4) * DOUT + o0];
                    ulonglong2 w0 = *reinterpret_cast<const ulonglong2*>(wb);
                    ulonglong2 w1 = *reinterpret_cast<const ulonglong2*>(wb + DOUT);
                    ulonglong2 w2 = *reinterpret_cast<const ulonglong2*>(wb + 2 * DOUT);
                    ulonglong2 w3 = *reinterpret_cast<const ulonglong2*>(wb + 3 * DOUT);
#pragma unroll
                    for (int k = 0; k < NPT; k++) {
                        float4 a = *reinterpret_cast<const float4*>(&sAcc[nb0 + k][r][i4 * 4]);
                        u64 aa;
                        aa = pack2(a.x); fma2(s01[k], aa, w0.x, s01[k]); fma2(s23[k], aa, w0.y, s23[k]);
                        aa = pack2(a.y); fma2(s01[k], aa, w1.x, s01[k]); fma2(s23[k], aa, w1.y, s23[k]);
                        aa = pack2(a.z); fma2(s01[k], aa, w2.x, s01[k]); fma2(s23[k], aa, w2.y, s23[k]);
                        aa = pack2(a.w); fma2(s01[k], aa, w3.x, s01[k]); fma2(s23[k], aa, w3.y, s23[k]);
                    }
                }
            }
#pragma unroll
            for (int k = 0; k < NPT; k++) {
                int n = node0 + nb0 + k;
                if (n < N_NODES) {
                    union { u64 q[2]; float f[4]; } sv;
                    sv.q[0] = s01[k]; sv.q[1] = s23[k];
                    if (RELU) {
#pragma unroll
                        for (int j = 0; j < 4; j++) sv.f[j] = fmaxf(sv.f[j], 0.f);
                    }
                    if (!POOL) {
                        *reinterpret_cast<float4*>(&hout[n * DOUT + o0]) =
                            make_float4(sv.f[0], sv.f[1], sv.f[2], sv.f[3]);
                    } else {
                        int g  = sBatch[nb0 + k];
                        int gr = g - sBatch[0];
#pragma unroll
                        for (int j = 0; j < 4; j++) {
                            unsigned ev = enc(sv.f[j]);
                            if (gr >= 0 && gr < GSLOT)
                                atomicMax(&sPool[gr * 64 + o0 + j], ev);
                            else
                                atomicMax(&g_pool[g * 64 + o0 + j], ev);
                        }
                    }
                }
            }
        }

        if (POOL) {
            __syncthreads();
            int g0 = sBatch[0];
            for (int i = threadIdx.x; i < GSLOT * 64; i += 256) {
                unsigned v = sPool[i];
                int g = g0 + i / 64;
                if (v != 0u && g < NG)
                    atomicMax(&g_pool[g * 64 + (i & 63)], v);
            }
        }
        __syncthreads();   // sAcc/sPool reuse barrier before next tile
    }
}

// ---- decode + restore pool ----
__global__ void decode_kernel(float* __restrict__ out) {
    int i = blockIdx.x * blockDim.x + threadIdx.x;
    if (i < NG * 64) {
        unsigned u = g_pool[i];
        out[i] = (u == 0u) ? __int_as_float(0xff800000) : dec(u);
        g_pool[i] = 0u;
    }
}

extern "C" void kernel_launch(void* const* d_in, const int* in_sizes, int n_in,
                              void* d_out, int out_size) {
    const float* x     = (const float*)d_in[0];
    const int*   ei    = (const int*)d_in[1];
    const int*   src   = ei;
    const int*   dst   = ei + N_EDGES;
    const int*   et    = (const int*)d_in[2];
    const int*   batch = (const int*)d_in[3];
    const float* W1 = (const float*)d_in[4];
    const float* r1 = (const float*)d_in[5];
    const float* b1 = (const float*)d_in[6];
    const float* W2 = (const float*)d_in[7];
    const float* r2 = (const float*)d_in[8];
    const float* b2 = (const float*)d_in[9];
    const float* W3 = (const float*)d_in[10];
    const float* r3 = (const float*)d_in[11];
    const float* b3 = (const float*)d_in[12];
    float* out = (float*)d_out;

    float *h1p, *h2p;
    cudaGetSymbolAddress((void**)&h1p, g_h1);
    cudaGetSymbolAddress((void**)&h2p, g_h2);

    const int T = 256;
    const int SMS = 148;

    count_kernel<<<(N_EDGES + T - 1) / T, T>>>(dst, et);         // 1
    scan_kernel<<<NT2, SCAN_T>>>();                              // 2
    fill_kernel<<<(N_EDGES + T - 1) / T, T>>>(src, dst, et);     // 3

    layer_kernel<16, 16, 64, true,  false, 4>                    // 4 <- profiled
        <<<SMS * 4, T>>>(x,   W1, r1, b1, h1p, nullptr);
    layer_kernel<16, 32, 64, true,  false, 4>
        <<<SMS * 4, T>>>(h1p, W2, r2, b2, h2p, nullptr);
    layer_kernel<32, 64, 32, false, true,  3>
        <<<SMS * 3, T>>>(h2p, W3, r3, b3, nullptr, batch);

    decode_kernel<<<(NG * 64 + T - 1) / T, T>>>(out);
}